// round 6
// baseline (speedup 1.0000x reference)
#include <cuda_runtime.h>
#include <cstdint>

// ============================================================================
// Problem dims
// ============================================================================
#define M_TOTAL 16384      // 4 * 4096 tokens
#define N_TOTAL 2048
#define K_TOTAL 2048
#define BM 128
#define BN 128
#define BK 128             // int8 -> 128 bytes per row
#define STAGES 3
#define KITERS (K_TOTAL / BK)             // 16
#define STAGE_A_BYTES (BM * BK)           // 16384
#define STAGE_BYTES   (STAGE_A_BYTES * 2) // 32768
#define SMEM_DYN (STAGES * STAGE_BYTES)   // 98304

// ============================================================================
// Scratch (static device globals: allocation-free)
// ============================================================================
__device__ int8_t g_xq[(size_t)M_TOTAL * K_TOTAL];   // 32 MB
__device__ int8_t g_w[(size_t)N_TOTAL * K_TOTAL];    // 4 MB
__device__ float  g_osc[M_TOTAL];

// ============================================================================
// PTX helpers (arch-generic: compile for compute_103)
// ============================================================================
__device__ __forceinline__ uint32_t smem_u32(const void* p) {
    uint32_t a;
    asm("{ .reg .u64 t; cvta.to.shared.u64 t, %1; cvt.u32.u64 %0, t; }"
        : "=r"(a) : "l"(p));
    return a;
}

__device__ __forceinline__ void cp_async16(uint32_t smem, const void* gmem) {
    asm volatile("cp.async.cg.shared.global [%0], [%1], 16;"
                 :: "r"(smem), "l"(gmem) : "memory");
}
__device__ __forceinline__ void cp_commit() {
    asm volatile("cp.async.commit_group;" ::: "memory");
}
template <int N>
__device__ __forceinline__ void cp_wait() {
    asm volatile("cp.async.wait_group %0;" :: "n"(N) : "memory");
}

__device__ __forceinline__ void ldsm4(uint32_t& r0, uint32_t& r1,
                                      uint32_t& r2, uint32_t& r3, uint32_t addr) {
    asm volatile("ldmatrix.sync.aligned.m8n8.x4.shared.b16 {%0,%1,%2,%3}, [%4];"
                 : "=r"(r0), "=r"(r1), "=r"(r2), "=r"(r3) : "r"(addr));
}

__device__ __forceinline__ void mma_s8(int* c,
                                       uint32_t a0, uint32_t a1, uint32_t a2, uint32_t a3,
                                       uint32_t b0, uint32_t b1) {
    asm volatile(
        "mma.sync.aligned.m16n8k32.row.col.s32.s8.s8.s32 "
        "{%0,%1,%2,%3}, {%4,%5,%6,%7}, {%8,%9}, {%0,%1,%2,%3};"
        : "+r"(c[0]), "+r"(c[1]), "+r"(c[2]), "+r"(c[3])
        : "r"(a0), "r"(a1), "r"(a2), "r"(a3), "r"(b0), "r"(b1));
}

// ============================================================================
// Kernel 1: per-token activation quantization (round-half-even, clamp to
// [-128,127]); xq int8, osc = amax / (127 * weight_scale)
// ============================================================================
__global__ void __launch_bounds__(256) quant_kernel(
    const float* __restrict__ x, const float* __restrict__ ws,
    int8_t* __restrict__ xq, float* __restrict__ osc)
{
    __shared__ float red[8];
    int t = blockIdx.x;
    int tid = threadIdx.x;
    const float4* xp = reinterpret_cast<const float4*>(x + (size_t)t * K_TOTAL);
    float4 a = xp[tid * 2];
    float4 b = xp[tid * 2 + 1];
    float m = fmaxf(fmaxf(fmaxf(fabsf(a.x), fabsf(a.y)), fmaxf(fabsf(a.z), fabsf(a.w))),
                    fmaxf(fmaxf(fabsf(b.x), fabsf(b.y)), fmaxf(fabsf(b.z), fabsf(b.w))));
    #pragma unroll
    for (int o = 16; o > 0; o >>= 1)
        m = fmaxf(m, __shfl_xor_sync(0xFFFFFFFFu, m, o));
    if ((tid & 31) == 0) red[tid >> 5] = m;
    __syncthreads();
    float mm = red[0];
    #pragma unroll
    for (int i = 1; i < 8; i++) mm = fmaxf(mm, red[i]);
    float amax = fmaxf(mm, 1e-5f);
    float scale = 127.0f / amax;

    float v[8] = {a.x, a.y, a.z, a.w, b.x, b.y, b.z, b.w};
    uint32_t lo = 0, hi = 0;
    #pragma unroll
    for (int i = 0; i < 4; i++) {
        int q = (int)fminf(fmaxf(rintf(v[i] * scale), -128.0f), 127.0f);
        lo |= ((uint32_t)q & 0xFF) << (8 * i);
    }
    #pragma unroll
    for (int i = 0; i < 4; i++) {
        int q = (int)fminf(fmaxf(rintf(v[4 + i] * scale), -128.0f), 127.0f);
        hi |= ((uint32_t)q & 0xFF) << (8 * i);
    }
    uint2 u = {lo, hi};
    reinterpret_cast<uint2*>(xq + (size_t)t * K_TOTAL)[tid] = u;

    if (tid == 0) osc[t] = amax / (127.0f * ws[0]);
}

// ============================================================================
// Kernel 2: 2-bit weight unpack (HF BitNet layout) -> int8 [N, K]
// out row o: group = o/512 (bits 2g,2g+1), packed row = o%512; value = bits-1
// ============================================================================
__global__ void __launch_bounds__(256) unpack_kernel(
    const int* __restrict__ wp, int8_t* __restrict__ w)
{
    int idx = blockIdx.x * 256 + threadIdx.x;     // 2048*256 threads total
    int o  = idx >> 8;                            // output row (0..2047)
    int kb = (idx & 255) << 3;                    // k base, 8 per thread
    int sh = 2 * (o >> 9);
    int r  = o & 511;
    const int4* p = reinterpret_cast<const int4*>(wp + (size_t)r * K_TOTAL + kb);
    int4 pa = p[0], pb = p[1];
    int vv[8] = {pa.x, pa.y, pa.z, pa.w, pb.x, pb.y, pb.z, pb.w};
    uint32_t lo = 0, hi = 0;
    #pragma unroll
    for (int i = 0; i < 4; i++) {
        int q = ((vv[i] >> sh) & 3) - 1;
        lo |= ((uint32_t)q & 0xFF) << (8 * i);
    }
    #pragma unroll
    for (int i = 0; i < 4; i++) {
        int q = ((vv[4 + i] >> sh) & 3) - 1;
        hi |= ((uint32_t)q & 0xFF) << (8 * i);
    }
    uint2 u = {lo, hi};
    *reinterpret_cast<uint2*>(w + (size_t)o * K_TOTAL + kb) = u;
}

// ============================================================================
// Kernel 3: int8 IMMA GEMM 128x128x(K=2048), 3-stage cp.async pipeline
// 8 warps: 4 along M (32 rows each) x 2 along N (64 cols each)
// smem: 128B rows, 16B chunks XOR-swizzled by (row & 7) -> conflict-free
// ============================================================================
__global__ void __launch_bounds__(256, 2) gemm_kernel(
    const int8_t* __restrict__ A, const int8_t* __restrict__ B,
    const float* __restrict__ osc, const float* __restrict__ bias,
    float* __restrict__ out)
{
    extern __shared__ int8_t smem[];
    const uint32_t sbase = smem_u32(smem);

    const int tid  = threadIdx.x;
    const int wid  = tid >> 5;
    const int lane = tid & 31;
    const int mt = blockIdx.x >> 4;   // 128 M tiles
    const int nt = blockIdx.x & 15;   // 16 N tiles

    const int wm = wid >> 1;          // 0..3 -> M offset wm*32
    const int wn = wid & 1;           // 0..1 -> N offset wn*64

    // --- cp.async addressing: each thread owns chunk (tid&7), rows tid>>3 + i*32
    const int lrow0 = tid >> 3;       // 0..31
    const int chunk = tid & 7;
    const int8_t* gA = A + ((size_t)(mt * BM + lrow0)) * K_TOTAL + chunk * 16;
    const int8_t* gB = B + ((size_t)(nt * BN + lrow0)) * K_TOTAL + chunk * 16;

    auto load_stage = [&](int s, int kt) {
        uint32_t sA = sbase + s * STAGE_BYTES;
        uint32_t sB = sA + STAGE_A_BYTES;
        const int8_t* pA = gA + kt * BK;
        const int8_t* pB = gB + kt * BK;
        #pragma unroll
        for (int i = 0; i < 4; i++) {
            int r = lrow0 + i * 32;
            uint32_t sw = (uint32_t)((chunk ^ (r & 7)) * 16);
            cp_async16(sA + r * 128 + sw, pA + (size_t)i * 32 * K_TOTAL);
            cp_async16(sB + r * 128 + sw, pB + (size_t)i * 32 * K_TOTAL);
        }
    };

    int acc[2][8][4];
    #pragma unroll
    for (int mi = 0; mi < 2; mi++)
        #pragma unroll
        for (int ni = 0; ni < 8; ni++)
            #pragma unroll
            for (int j = 0; j < 4; j++) acc[mi][ni][j] = 0;

    // ldmatrix lane addressing
    const int lrow = lane & 15;
    const int lhalf = lane >> 4;       // 0/1 -> +16B in k

    // --- prologue
    load_stage(0, 0); cp_commit();
    load_stage(1, 1); cp_commit();

    for (int k = 0; k < KITERS; k++) {
        if (k + STAGES - 1 < KITERS)
            load_stage((k + STAGES - 1) % STAGES, k + STAGES - 1);
        cp_commit();
        cp_wait<STAGES - 1>();
        __syncthreads();

        uint32_t sA = sbase + (k % STAGES) * STAGE_BYTES;
        uint32_t sB = sA + STAGE_A_BYTES;

        #pragma unroll
        for (int ks = 0; ks < 4; ks++) {          // 4 x k32 per 128B stage
            uint32_t a[2][4];
            #pragma unroll
            for (int mi = 0; mi < 2; mi++) {
                int r = wm * 32 + mi * 16 + lrow;
                uint32_t addr = sA + r * 128 + (((ks * 2 + lhalf) ^ (r & 7)) * 16);
                ldsm4(a[mi][0], a[mi][1], a[mi][2], a[mi][3], addr);
            }
            uint32_t bb[4][4];
            #pragma unroll
            for (int p = 0; p < 4; p++) {
                int r = wn * 64 + p * 16 + lrow;
                uint32_t addr = sB + r * 128 + (((ks * 2 + lhalf) ^ (r & 7)) * 16);
                ldsm4(bb[p][0], bb[p][1], bb[p][2], bb[p][3], addr);
            }
            #pragma unroll
            for (int mi = 0; mi < 2; mi++)
                #pragma unroll
                for (int p = 0; p < 4; p++) {
                    mma_s8(acc[mi][2 * p],     a[mi][0], a[mi][1], a[mi][2], a[mi][3],
                           bb[p][0], bb[p][2]);
                    mma_s8(acc[mi][2 * p + 1], a[mi][0], a[mi][1], a[mi][2], a[mi][3],
                           bb[p][1], bb[p][3]);
                }
        }
        __syncthreads();
    }

    // --- epilogue: y = acc * osc[m] + bias[n]
    const int gr = lane >> 2;       // 0..7
    const int gc = lane & 3;        // 0..3
    const int ncol0 = nt * BN + wn * 64;
    #pragma unroll
    for (int mi = 0; mi < 2; mi++) {
        int r0 = mt * BM + wm * 32 + mi * 16 + gr;
        float s0 = osc[r0];
        float s1 = osc[r0 + 8];
        float* o0 = out + (size_t)r0 * N_TOTAL + ncol0;
        float* o1 = o0 + (size_t)8 * N_TOTAL;
        #pragma unroll
        for (int ni = 0; ni < 8; ni++) {
            float2 bv = *reinterpret_cast<const float2*>(bias + ncol0 + ni * 8 + gc * 2);
            int* c = acc[mi][ni];
            float2 v0 = {(float)c[0] * s0 + bv.x, (float)c[1] * s0 + bv.y};
            float2 v1 = {(float)c[2] * s1 + bv.x, (float)c[3] * s1 + bv.y};
            *reinterpret_cast<float2*>(o0 + ni * 8 + gc * 2) = v0;
            *reinterpret_cast<float2*>(o1 + ni * 8 + gc * 2) = v1;
        }
    }
}

// ============================================================================
// Host launch
// ============================================================================
extern "C" void kernel_launch(void* const* d_in, const int* in_sizes, int n_in,
                              void* d_out, int out_size)
{
    const float* x    = (const float*)d_in[0];
    const int*   wp   = (const int*)d_in[1];
    const float* ws   = (const float*)d_in[2];
    const float* bias = (const float*)d_in[3];
    float* out = (float*)d_out;

    void *pxq = nullptr, *pw = nullptr, *posc = nullptr;
    cudaGetSymbolAddress(&pxq, g_xq);
    cudaGetSymbolAddress(&pw, g_w);
    cudaGetSymbolAddress(&posc, g_osc);

    static bool configured = false;
    if (!configured) {
        cudaFuncSetAttribute(gemm_kernel,
                             cudaFuncAttributeMaxDynamicSharedMemorySize, SMEM_DYN);
        configured = true;
    }

    quant_kernel<<<M_TOTAL, 256>>>(x, ws, (int8_t*)pxq, (float*)posc);
    unpack_kernel<<<(N_TOTAL * K_TOTAL / 8) / 256, 256>>>(wp, (int8_t*)pw);
    gemm_kernel<<<(M_TOTAL / BM) * (N_TOTAL / BN), 256, SMEM_DYN>>>(
        (const int8_t*)pxq, (const int8_t*)pw, (const float*)posc, bias, out);
}

// round 7
// speedup vs baseline: 3.9011x; 3.9011x over previous
#include <cuda_runtime.h>
#include <cuda_bf16.h>
#include <cstdint>

// ============================================================================
// Problem dims
// ============================================================================
#define M_TOTAL 16384      // 4 * 4096 tokens
#define N_TOTAL 2048
#define K_TOTAL 2048
#define BM 128
#define BN 128
#define BK 64              // bf16 elems -> 128 bytes per smem row
#define STAGES 3
#define KITERS (K_TOTAL / BK)             // 32
#define STAGE_A_BYTES (BM * 128)          // 16384
#define STAGE_BYTES   (STAGE_A_BYTES * 2) // 32768
#define SMEM_DYN (STAGES * STAGE_BYTES)   // 98304

// ============================================================================
// Scratch (static device globals: allocation-free)
// ============================================================================
__device__ __nv_bfloat16 g_xq[(size_t)M_TOTAL * K_TOTAL];   // 64 MB
__device__ __nv_bfloat16 g_w[(size_t)N_TOTAL * K_TOTAL];    // 8 MB
__device__ float         g_osc[M_TOTAL];

// ============================================================================
// PTX helpers (arch-generic: compile for compute_103)
// ============================================================================
__device__ __forceinline__ uint32_t smem_u32(const void* p) {
    uint32_t a;
    asm("{ .reg .u64 t; cvta.to.shared.u64 t, %1; cvt.u32.u64 %0, t; }"
        : "=r"(a) : "l"(p));
    return a;
}

__device__ __forceinline__ void cp_async16(uint32_t smem, const void* gmem) {
    asm volatile("cp.async.cg.shared.global [%0], [%1], 16;"
                 :: "r"(smem), "l"(gmem) : "memory");
}
__device__ __forceinline__ void cp_commit() {
    asm volatile("cp.async.commit_group;" ::: "memory");
}
template <int N>
__device__ __forceinline__ void cp_wait() {
    asm volatile("cp.async.wait_group %0;" :: "n"(N) : "memory");
}

__device__ __forceinline__ void ldsm4(uint32_t& r0, uint32_t& r1,
                                      uint32_t& r2, uint32_t& r3, uint32_t addr) {
    asm volatile("ldmatrix.sync.aligned.m8n8.x4.shared.b16 {%0,%1,%2,%3}, [%4];"
                 : "=r"(r0), "=r"(r1), "=r"(r2), "=r"(r3) : "r"(addr));
}

// bf16 HMMA with fp32 accumulate — the documented native fallback path on sm_103
__device__ __forceinline__ void mma_bf16(float* c,
                                         uint32_t a0, uint32_t a1, uint32_t a2, uint32_t a3,
                                         uint32_t b0, uint32_t b1) {
    asm volatile(
        "mma.sync.aligned.m16n8k16.row.col.f32.bf16.bf16.f32 "
        "{%0,%1,%2,%3}, {%4,%5,%6,%7}, {%8,%9}, {%0,%1,%2,%3};"
        : "+f"(c[0]), "+f"(c[1]), "+f"(c[2]), "+f"(c[3])
        : "r"(a0), "r"(a1), "r"(a2), "r"(a3), "r"(b0), "r"(b1));
}

// ============================================================================
// Kernel 1: per-token activation quantization (round-half-even, clamp to
// [-128,127]); xq bf16 (exact for these integers), osc = amax/(127*ws)
// ============================================================================
__global__ void __launch_bounds__(256) quant_kernel(
    const float* __restrict__ x, const float* __restrict__ ws,
    __nv_bfloat16* __restrict__ xq, float* __restrict__ osc)
{
    __shared__ float red[8];
    int t = blockIdx.x;
    int tid = threadIdx.x;
    const float4* xp = reinterpret_cast<const float4*>(x + (size_t)t * K_TOTAL);
    float4 a = xp[tid * 2];
    float4 b = xp[tid * 2 + 1];
    float m = fmaxf(fmaxf(fmaxf(fabsf(a.x), fabsf(a.y)), fmaxf(fabsf(a.z), fabsf(a.w))),
                    fmaxf(fmaxf(fabsf(b.x), fabsf(b.y)), fmaxf(fabsf(b.z), fabsf(b.w))));
    #pragma unroll
    for (int o = 16; o > 0; o >>= 1)
        m = fmaxf(m, __shfl_xor_sync(0xFFFFFFFFu, m, o));
    if ((tid & 31) == 0) red[tid >> 5] = m;
    __syncthreads();
    float mm = red[0];
    #pragma unroll
    for (int i = 1; i < 8; i++) mm = fmaxf(mm, red[i]);
    float amax = fmaxf(mm, 1e-5f);
    float scale = 127.0f / amax;

    float v[8] = {a.x, a.y, a.z, a.w, b.x, b.y, b.z, b.w};
    unsigned short us[8];
    #pragma unroll
    for (int i = 0; i < 8; i++) {
        float q = fminf(fmaxf(rintf(v[i] * scale), -128.0f), 127.0f);
        us[i] = __bfloat16_as_ushort(__float2bfloat16(q));
    }
    uint4 u;
    u.x = (uint32_t)us[0] | ((uint32_t)us[1] << 16);
    u.y = (uint32_t)us[2] | ((uint32_t)us[3] << 16);
    u.z = (uint32_t)us[4] | ((uint32_t)us[5] << 16);
    u.w = (uint32_t)us[6] | ((uint32_t)us[7] << 16);
    reinterpret_cast<uint4*>(xq + (size_t)t * K_TOTAL)[tid] = u;

    if (tid == 0) osc[t] = amax / (127.0f * ws[0]);
}

// ============================================================================
// Kernel 2: 2-bit weight unpack (HF BitNet layout) -> bf16 [N, K]
// out row o: group = o/512 (bits 2g,2g+1), packed row = o%512; value = bits-1
// ============================================================================
__global__ void __launch_bounds__(256) unpack_kernel(
    const int* __restrict__ wp, __nv_bfloat16* __restrict__ w)
{
    int idx = blockIdx.x * 256 + threadIdx.x;     // N*K/8 threads total
    int o  = idx >> 8;                            // output row (0..2047)
    int kb = (idx & 255) << 3;                    // k base, 8 per thread
    int sh = 2 * (o >> 9);
    int r  = o & 511;
    const int4* p = reinterpret_cast<const int4*>(wp + (size_t)r * K_TOTAL + kb);
    int4 pa = p[0], pb = p[1];
    int vv[8] = {pa.x, pa.y, pa.z, pa.w, pb.x, pb.y, pb.z, pb.w};
    unsigned short us[8];
    #pragma unroll
    for (int i = 0; i < 8; i++) {
        float f = (float)(((vv[i] >> sh) & 3) - 1);
        us[i] = __bfloat16_as_ushort(__float2bfloat16(f));
    }
    uint4 u;
    u.x = (uint32_t)us[0] | ((uint32_t)us[1] << 16);
    u.y = (uint32_t)us[2] | ((uint32_t)us[3] << 16);
    u.z = (uint32_t)us[4] | ((uint32_t)us[5] << 16);
    u.w = (uint32_t)us[6] | ((uint32_t)us[7] << 16);
    *reinterpret_cast<uint4*>(w + (size_t)o * K_TOTAL + kb) = u;
}

// ============================================================================
// Kernel 3: bf16 HMMA GEMM 128x128x(K=2048), 3-stage cp.async pipeline
// 8 warps: 4 along M (32 rows each) x 2 along N (64 cols each)
// smem: 128B rows, 16B chunks XOR-swizzled by (row & 7) -> conflict-free
// ============================================================================
__global__ void __launch_bounds__(256, 2) gemm_kernel(
    const __nv_bfloat16* __restrict__ A, const __nv_bfloat16* __restrict__ B,
    const float* __restrict__ osc, const float* __restrict__ bias,
    float* __restrict__ out)
{
    extern __shared__ int8_t smem[];
    const uint32_t sbase = smem_u32(smem);

    const int tid  = threadIdx.x;
    const int wid  = tid >> 5;
    const int lane = tid & 31;
    const int mt = blockIdx.x >> 4;   // 128 M tiles
    const int nt = blockIdx.x & 15;   // 16 N tiles

    const int wm = wid >> 1;          // 0..3 -> M offset wm*32
    const int wn = wid & 1;           // 0..1 -> N offset wn*64

    // cp.async addressing: each thread owns 16B chunk (tid&7), rows tid>>3 + i*32
    const int lrow0 = tid >> 3;       // 0..31
    const int chunk = tid & 7;
    const __nv_bfloat16* gA = A + ((size_t)(mt * BM + lrow0)) * K_TOTAL + chunk * 8;
    const __nv_bfloat16* gB = B + ((size_t)(nt * BN + lrow0)) * K_TOTAL + chunk * 8;

    auto load_stage = [&](int s, int kt) {
        uint32_t sA = sbase + s * STAGE_BYTES;
        uint32_t sB = sA + STAGE_A_BYTES;
        const __nv_bfloat16* pA = gA + kt * BK;
        const __nv_bfloat16* pB = gB + kt * BK;
        #pragma unroll
        for (int i = 0; i < 4; i++) {
            int r = lrow0 + i * 32;
            uint32_t sw = (uint32_t)((chunk ^ (r & 7)) * 16);
            cp_async16(sA + r * 128 + sw, pA + (size_t)i * 32 * K_TOTAL);
            cp_async16(sB + r * 128 + sw, pB + (size_t)i * 32 * K_TOTAL);
        }
    };

    float acc[2][8][4];
    #pragma unroll
    for (int mi = 0; mi < 2; mi++)
        #pragma unroll
        for (int ni = 0; ni < 8; ni++)
            #pragma unroll
            for (int j = 0; j < 4; j++) acc[mi][ni][j] = 0.0f;

    // ldmatrix lane addressing: 16 rows x 2 k16-halves
    const int lrow = lane & 15;
    const int lhalf = lane >> 4;       // 0/1 -> +16B in k

    // --- prologue
    load_stage(0, 0); cp_commit();
    load_stage(1, 1); cp_commit();

    for (int k = 0; k < KITERS; k++) {
        if (k + STAGES - 1 < KITERS)
            load_stage((k + STAGES - 1) % STAGES, k + STAGES - 1);
        cp_commit();
        cp_wait<STAGES - 1>();
        __syncthreads();

        uint32_t sA = sbase + (k % STAGES) * STAGE_BYTES;
        uint32_t sB = sA + STAGE_A_BYTES;

        #pragma unroll
        for (int ks = 0; ks < 4; ks++) {          // 4 x k16 per 128B stage row
            uint32_t a[2][4];
            #pragma unroll
            for (int mi = 0; mi < 2; mi++) {
                int r = wm * 32 + mi * 16 + lrow;
                uint32_t addr = sA + r * 128 + (((ks * 2 + lhalf) ^ (r & 7)) * 16);
                ldsm4(a[mi][0], a[mi][1], a[mi][2], a[mi][3], addr);
            }
            uint32_t bb[4][4];
            #pragma unroll
            for (int p = 0; p < 4; p++) {
                int r = wn * 64 + p * 16 + lrow;
                uint32_t addr = sB + r * 128 + (((ks * 2 + lhalf) ^ (r & 7)) * 16);
                ldsm4(bb[p][0], bb[p][1], bb[p][2], bb[p][3], addr);
            }
            #pragma unroll
            for (int mi = 0; mi < 2; mi++)
                #pragma unroll
                for (int p = 0; p < 4; p++) {
                    mma_bf16(acc[mi][2 * p],     a[mi][0], a[mi][1], a[mi][2], a[mi][3],
                             bb[p][0], bb[p][2]);
                    mma_bf16(acc[mi][2 * p + 1], a[mi][0], a[mi][1], a[mi][2], a[mi][3],
                             bb[p][1], bb[p][3]);
                }
        }
        __syncthreads();
    }

    // --- epilogue: y = acc * osc[m] + bias[n]
    const int gr = lane >> 2;       // 0..7
    const int gc = lane & 3;        // 0..3
    const int ncol0 = nt * BN + wn * 64;
    #pragma unroll
    for (int mi = 0; mi < 2; mi++) {
        int r0 = mt * BM + wm * 32 + mi * 16 + gr;
        float s0 = osc[r0];
        float s1 = osc[r0 + 8];
        float* o0 = out + (size_t)r0 * N_TOTAL + ncol0;
        float* o1 = o0 + (size_t)8 * N_TOTAL;
        #pragma unroll
        for (int ni = 0; ni < 8; ni++) {
            float2 bv = *reinterpret_cast<const float2*>(bias + ncol0 + ni * 8 + gc * 2);
            float* c = acc[mi][ni];
            float2 v0 = {c[0] * s0 + bv.x, c[1] * s0 + bv.y};
            float2 v1 = {c[2] * s1 + bv.x, c[3] * s1 + bv.y};
            *reinterpret_cast<float2*>(o0 + ni * 8 + gc * 2) = v0;
            *reinterpret_cast<float2*>(o1 + ni * 8 + gc * 2) = v1;
        }
    }
}

// ============================================================================
// Host launch
// ============================================================================
extern "C" void kernel_launch(void* const* d_in, const int* in_sizes, int n_in,
                              void* d_out, int out_size)
{
    const float* x    = (const float*)d_in[0];
    const int*   wp   = (const int*)d_in[1];
    const float* ws   = (const float*)d_in[2];
    const float* bias = (const float*)d_in[3];
    float* out = (float*)d_out;

    void *pxq = nullptr, *pw = nullptr, *posc = nullptr;
    cudaGetSymbolAddress(&pxq, g_xq);
    cudaGetSymbolAddress(&pw, g_w);
    cudaGetSymbolAddress(&posc, g_osc);

    static bool configured = false;
    if (!configured) {
        cudaFuncSetAttribute(gemm_kernel,
                             cudaFuncAttributeMaxDynamicSharedMemorySize, SMEM_DYN);
        configured = true;
    }

    quant_kernel<<<M_TOTAL, 256>>>(x, ws, (__nv_bfloat16*)pxq, (float*)posc);
    unpack_kernel<<<(N_TOTAL * K_TOTAL / 8) / 256, 256>>>(wp, (__nv_bfloat16*)pw);
    gemm_kernel<<<(M_TOTAL / BM) * (N_TOTAL / BN), 256, SMEM_DYN>>>(
        (const __nv_bfloat16*)pxq, (const __nv_bfloat16*)pw,
        (const float*)posc, bias, out);
}